// round 15
// baseline (speedup 1.0000x reference)
#include <cuda_runtime.h>
#include <cuda_bf16.h>
#include <cuda_fp16.h>
#include <cstdint>

// ---------------- problem constants ----------------
#define BB   4
#define IMGD 256
#define HID  64
#define PH   63
#define NPAT 3969
#define PPF  64
#define GHD  128
#define KPAD 4032
#define NCHUNK 63   // KPAD / 64

// ---------------- scratch ----------------
__device__ __half g_h1i[(long)BB*IMGD*IMGD*HID];
__device__ __half g_h2h[(long)BB*HID*IMGD*IMGD];
__device__ float g_tmp2[BB*IMGD*IMGD];
__device__ float g_patch[BB*NPAT*PPF];
__device__ float g_g[(long)BB*NPAT*GHD];
__device__ float g_g2[(long)BB*NPAT*PPF];
__device__ __nv_bfloat16 g_adjb[(long)BB*NPAT*KPAD];
__device__ __nv_bfloat16 g_supT[(long)BB*GHD*KPAD];
__device__ __nv_bfloat16 g_gsupT[(long)BB*PPF*KPAD];
__device__ __half g_w2t[9*64*64];

__device__ __forceinline__ uint32_t smem_to_u32(const void* p) {
    uint32_t a;
    asm("{ .reg .u64 t; cvta.to.shared.u64 t, %1; cvt.u32.u64 %0, t; }"
        : "=r"(a) : "l"(p));
    return a;
}
__device__ __forceinline__ void ldmatrix_x4(uint32_t* r, uint32_t addr) {
    asm volatile("ldmatrix.sync.aligned.m8n8.x4.shared.b16 {%0,%1,%2,%3}, [%4];"
                 : "=r"(r[0]), "=r"(r[1]), "=r"(r[2]), "=r"(r[3]) : "r"(addr));
}
__device__ __forceinline__ void ldmatrix_x2(uint32_t* r, uint32_t addr) {
    asm volatile("ldmatrix.sync.aligned.m8n8.x2.shared.b16 {%0,%1}, [%2];"
                 : "=r"(r[0]), "=r"(r[1]) : "r"(addr));
}
__device__ __forceinline__ void mma16816_bf16(float* d, const uint32_t* a, const uint32_t* b) {
    asm volatile(
        "mma.sync.aligned.m16n8k16.row.col.f32.bf16.bf16.f32 "
        "{%0,%1,%2,%3}, {%4,%5,%6,%7}, {%8,%9}, {%0,%1,%2,%3};"
        : "+f"(d[0]), "+f"(d[1]), "+f"(d[2]), "+f"(d[3])
        : "r"(a[0]), "r"(a[1]), "r"(a[2]), "r"(a[3]), "r"(b[0]), "r"(b[1]));
}
__device__ __forceinline__ void mma16816_f16(float* d, const uint32_t* a, const uint32_t* b) {
    asm volatile(
        "mma.sync.aligned.m16n8k16.row.col.f32.f16.f16.f32 "
        "{%0,%1,%2,%3}, {%4,%5,%6,%7}, {%8,%9}, {%0,%1,%2,%3};"
        : "+f"(d[0]), "+f"(d[1]), "+f"(d[2]), "+f"(d[3])
        : "r"(a[0]), "r"(a[1]), "r"(a[2]), "r"(a[3]), "r"(b[0]), "r"(b[1]));
}
__device__ __forceinline__ void cp_async16(uint32_t dst, const void* src, uint32_t bytes) {
    asm volatile("cp.async.cg.shared.global [%0], [%1], 16, %2;"
                 :: "r"(dst), "l"(src), "r"(bytes));
}
#define CP_COMMIT() asm volatile("cp.async.commit_group;" ::: "memory")
#define CP_WAIT(n)  asm volatile("cp.async.wait_group %0;" :: "n"(n) : "memory")

// ==================== weight transform ====================
__global__ void wt_kernel(const float* __restrict__ w2) {
    int idx = blockIdx.x * 256 + threadIdx.x;
    if (idx >= 64 * 64 * 9) return;
    int oc = idx / 576, r = idx - oc * 576;
    int ic = r / 9, t = r - ic * 9;
    g_w2t[t * 4096 + oc * 64 + ic] = __float2half(w2[idx]);
}

// ==================== conv1 ====================
__global__ void __launch_bounds__(256) conv1_kernel(const float* __restrict__ in,
                             const float* __restrict__ w,
                             const float* __restrict__ bias) {
    __shared__ float sIn[18][18];
    __shared__ float sW[576];
    __shared__ float sB[64];
    __shared__ __half sOut[16 * 16 * 64];
    int b = blockIdx.z;
    int x0 = blockIdx.x * 16, y0 = blockIdx.y * 16;
    int tid = threadIdx.x;
    for (int i = tid; i < 576; i += 256) sW[i] = w[i];
    if (tid < 64) sB[tid] = bias[tid];
    for (int i = tid; i < 324; i += 256) {
        int yy = i / 18, xx = i - yy * 18;
        int gy = y0 + yy - 1, gx = x0 + xx - 1;
        float v = 0.f;
        if (gy >= 0 && gy < IMGD && gx >= 0 && gx < IMGD)
            v = in[(long)b * IMGD * IMGD + gy * IMGD + gx];
        sIn[yy][xx] = v;
    }
    __syncthreads();
    int tx = tid & 15, ty = tid >> 4;
    float r[9];
#pragma unroll
    for (int dy = 0; dy < 3; dy++)
#pragma unroll
        for (int dx = 0; dx < 3; dx++)
            r[dy * 3 + dx] = sIn[ty + dy][tx + dx];
#pragma unroll 1
    for (int oc0 = 0; oc0 < 64; oc0 += 8) {
        __half hv[8];
#pragma unroll
        for (int o = 0; o < 8; o++) {
            float acc = sB[oc0 + o];
#pragma unroll
            for (int t = 0; t < 9; t++) acc += r[t] * sW[(oc0 + o) * 9 + t];
            hv[o] = __float2half(fmaxf(acc, 0.f));
        }
        *(uint4*)&sOut[tid * 64 + oc0] = *(uint4*)hv;
    }
    __syncthreads();
    for (int i = tid; i < 2048; i += 256) {
        int row = i >> 7;
        int c = i & 127;
        long e = (((long)b * IMGD * IMGD + (y0 + row) * IMGD + x0) << 6) + c * 8;
        *(uint4*)&g_h1i[e] = *(uint4*)&sOut[row * 1024 + c * 8];
    }
}

// ==================== conv2 body (device fn) ====================
#define C2_XH (340 * 72)
#define C2_WH (64 * 72)
__device__ __forceinline__ void conv2_body(int bx, int by, int b,
                                           const float* __restrict__ bias,
                                           __half* dsm) {
    __half* X_s = dsm;
    __half* W_s[2] = {dsm + C2_XH, dsm + C2_XH + C2_WH};
    int tid = threadIdx.x, lane = tid & 31, wid = tid >> 5;
    int y0 = by * 8, x0 = bx * 32;
    int wm = (wid & 3) * 64;
    int wn = (wid >> 2) * 32;

    for (int i = tid; i < 2720; i += 256) {
        int pos = i >> 3, q = i & 7;
        int row = pos / 34, col = pos - row * 34;
        int gy = y0 + row - 1, gx = x0 + col - 1;
        uint4 v = make_uint4(0u, 0u, 0u, 0u);
        if (gy >= 0 && gy < IMGD && gx >= 0 && gx < IMGD)
            v = *(const uint4*)&g_h1i[(((long)b * IMGD * IMGD + gy * IMGD + gx) << 6) + q * 8];
        *(uint4*)&X_s[pos * 72 + q * 8] = v;
    }
    for (int i = tid; i < 512; i += 256) {
        int oc = i >> 3, q = i & 7;
        *(uint4*)&W_s[0][oc * 72 + q * 8] = *(const uint4*)&g_w2t[oc * 64 + q * 8];
    }
    __syncthreads();

    float acc[4][4][4];
#pragma unroll
    for (int i = 0; i < 4; i++)
#pragma unroll
        for (int j = 0; j < 4; j++)
#pragma unroll
            for (int q = 0; q < 4; q++) acc[i][j][q] = 0.f;

    uint32_t xb = smem_to_u32(X_s);
    uint32_t wb[2] = {smem_to_u32(W_s[0]), smem_to_u32(W_s[1])};

    uint32_t abase[4];
#pragma unroll
    for (int am = 0; am < 4; am++) {
        int p0 = wm + am * 16;
        abase[am] = xb + (uint32_t)((((p0 >> 5) * 34) + (p0 & 31) + (lane & 15)) * 144)
                       + (uint32_t)((lane >> 4) * 16);
    }
    uint32_t bbase[4];
#pragma unroll
    for (int an = 0; an < 4; an++)
        bbase[an] = (uint32_t)((wn + an * 8 + (lane & 7)) * 144)
                  + (uint32_t)(((lane >> 3) & 1) * 16);

    for (int tap = 0; tap < 9; tap++) {
        int cur = tap & 1;
        if (tap < 8) {
            const __half* src = g_w2t + (tap + 1) * 4096;
            for (int i = tid; i < 512; i += 256) {
                int oc = i >> 3, q = i & 7;
                *(uint4*)&W_s[cur ^ 1][oc * 72 + q * 8] = *(const uint4*)&src[oc * 64 + q * 8];
            }
        }
        int dy = tap / 3, dx = tap - dy * 3;
        uint32_t toff = (uint32_t)((dy * 34 + dx) * 144);
#pragma unroll
        for (int kb = 0; kb < 64; kb += 16) {
            uint32_t af[4][4], bf[4][2];
#pragma unroll
            for (int am = 0; am < 4; am++)
                ldmatrix_x4(af[am], abase[am] + toff + kb * 2);
#pragma unroll
            for (int an = 0; an < 4; an++)
                ldmatrix_x2(bf[an], wb[cur] + bbase[an] + kb * 2);
#pragma unroll
            for (int am = 0; am < 4; am++)
#pragma unroll
                for (int an = 0; an < 4; an++)
                    mma16816_f16(acc[am][an], af[am], bf[an]);
        }
        __syncthreads();
    }

    int r0 = lane >> 2, c0l = (lane & 3) * 2;
#pragma unroll
    for (int am = 0; am < 4; am++) {
#pragma unroll
        for (int an = 0; an < 4; an++) {
            int oc = wn + an * 8 + c0l;
            float b0 = bias[oc], b1 = bias[oc + 1];
#pragma unroll
            for (int h = 0; h < 2; h++) {
                int p = wm + am * 16 + r0 + h * 8;
                int rr = p >> 5, cc = p & 31;
                long o = (((long)b * HID + oc) << 16) + ((y0 + rr) << 8) + (x0 + cc);
                g_h2h[o] = __float2half(fmaxf(acc[am][an][h * 2 + 0] + b0, 0.f));
                g_h2h[o + (1L << 16)] = __float2half(fmaxf(acc[am][an][h * 2 + 1] + b1, 0.f));
            }
        }
    }
}

// ==================== big HMMA GEMM body (device fn) ====================
#define LDT 72
#define STAGES 3

template<int NN, int BM>
__device__ __forceinline__ void gemm_body(int mblk, int bz,
        const __nv_bfloat16* __restrict__ A,
        const __nv_bfloat16* __restrict__ B,
        float* __restrict__ C,
        const float* __restrict__ bias, int relu,
        __nv_bfloat16* gsm) {
    constexpr int WNw = NN / 2;
    constexpr int NA = WNw / 8;
    constexpr int MW = BM / 2;
    constexpr int AM = MW / 16;
    constexpr int ASTG = BM * LDT;
    constexpr int BSTG = NN * LDT;
    constexpr int NAU = BM / 32;
    constexpr int NBU = NN * 8 / 256;
    constexpr int RSTR = WNw + 1;
    __nv_bfloat16* A_s = gsm;
    __nv_bfloat16* B_s = gsm + STAGES * ASTG;

    int tid = threadIdx.x;
    int lane = tid & 31;
    int wid = tid >> 5;
    int mi = wid & 1, ni = (wid >> 1) & 1, kg = wid >> 2;
    int wm = mi * MW;
    int wn = ni * WNw;
    int m0 = mblk * BM;

    const __nv_bfloat16* Ab = A + (long)bz * NPAT * KPAD;
    const __nv_bfloat16* Bb = B + (long)bz * NN * KPAD;
    float* Cb = C + (long)bz * NPAT * NN;

    float acc[AM][NA][4];
#pragma unroll
    for (int i = 0; i < AM; i++)
#pragma unroll
        for (int j = 0; j < NA; j++)
#pragma unroll
            for (int q = 0; q < 4; q++) acc[i][j][q] = 0.f;

    int a_row[NAU], a_part[NAU];
    uint32_t a_dst[NAU], a_bytes[NAU];
    const __nv_bfloat16* a_src[NAU];
#pragma unroll
    for (int l = 0; l < NAU; l++) {
        int u = tid + l * 256;
        a_row[l] = u >> 3; a_part[l] = u & 7;
        int gm = m0 + a_row[l];
        a_bytes[l] = (gm < NPAT) ? 16u : 0u;
        int gmc = gm < NPAT ? gm : NPAT - 1;
        a_src[l] = Ab + (long)gmc * KPAD + a_part[l] * 8;
        a_dst[l] = smem_to_u32(&A_s[a_row[l] * LDT + a_part[l] * 8]);
    }
    uint32_t b_dst[NBU];
    const __nv_bfloat16* b_src[NBU];
#pragma unroll
    for (int l = 0; l < NBU; l++) {
        int u = tid + l * 256;
        int row = u >> 3, part = u & 7;
        b_src[l] = Bb + (long)row * KPAD + part * 8;
        b_dst[l] = smem_to_u32(&B_s[row * LDT + part * 8]);
    }

    auto issue = [&](int c) {
        int s = c % STAGES;
        long kb = (long)c * 64;
#pragma unroll
        for (int l = 0; l < NAU; l++)
            cp_async16(a_dst[l] + s * (ASTG * 2), a_src[l] + kb, a_bytes[l]);
#pragma unroll
        for (int l = 0; l < NBU; l++)
            cp_async16(b_dst[l] + s * (BSTG * 2), b_src[l] + kb, 16u);
        CP_COMMIT();
    };

#pragma unroll
    for (int s = 0; s < STAGES - 1; s++) issue(s);

    uint32_t a_base0 = smem_to_u32(A_s);
    uint32_t b_base0 = smem_to_u32(B_s);
    uint32_t kks = (uint32_t)(kg * 64);

    for (int c = 0; c < NCHUNK; c++) {
        CP_WAIT(STAGES - 2);
        __syncthreads();
        int s = c % STAGES;
        uint32_t a_base = a_base0 + s * (ASTG * 2);
        uint32_t b_base = b_base0 + s * (BSTG * 2);
#pragma unroll
        for (int ks = 0; ks < 2; ks++) {
            uint32_t af[AM][4];
#pragma unroll
            for (int am = 0; am < AM; am++) {
                uint32_t addr = a_base +
                    (uint32_t)((wm + am * 16 + (lane & 15)) * (LDT * 2)) +
                    kks + (uint32_t)(ks * 32 + (lane >> 4) * 16);
                ldmatrix_x4(af[am], addr);
            }
            uint32_t bf[NA][2];
#pragma unroll
            for (int an = 0; an < NA; an++) {
                uint32_t addr = b_base +
                    (uint32_t)((wn + an * 8 + (lane & 7)) * (LDT * 2)) +
                    kks + (uint32_t)(ks * 32 + ((lane >> 3) & 1) * 16);
                ldmatrix_x2(bf[an], addr);
            }
#pragma unroll
            for (int am = 0; am < AM; am++)
#pragma unroll
                for (int an = 0; an < NA; an++)
                    mma16816_bf16(acc[am][an], af[am], bf[an]);
        }
        if (c + STAGES - 1 < NCHUNK) issue(c + STAGES - 1);
        else CP_COMMIT();
    }

    CP_WAIT(0);
    __syncthreads();
    int r0 = lane >> 2, c0 = (lane & 3) * 2;
    float* red = (float*)gsm;
    int region = (mi * 2 + ni) * (MW * RSTR);
    if (kg == 1) {
#pragma unroll
        for (int am = 0; am < AM; am++)
#pragma unroll
            for (int an = 0; an < NA; an++)
#pragma unroll
                for (int q = 0; q < 4; q++) {
                    int row = am * 16 + r0 + ((q >> 1) << 3);
                    int col = an * 8 + c0 + (q & 1);
                    red[region + row * RSTR + col] = acc[am][an][q];
                }
    }
    __syncthreads();
    if (kg == 0) {
#pragma unroll
        for (int am = 0; am < AM; am++)
#pragma unroll
            for (int an = 0; an < NA; an++)
#pragma unroll
                for (int q = 0; q < 4; q++) {
                    int row = am * 16 + r0 + ((q >> 1) << 3);
                    int col = an * 8 + c0 + (q & 1);
                    acc[am][an][q] += red[region + row * RSTR + col];
                }
#pragma unroll
        for (int am = 0; am < AM; am++) {
#pragma unroll
            for (int an = 0; an < NA; an++) {
                int gn = wn + an * 8 + c0;
                float b0 = bias[gn], b1 = bias[gn + 1];
                int gr0 = m0 + wm + am * 16 + r0;
                float v0 = acc[am][an][0] + b0;
                float v1 = acc[am][an][1] + b1;
                float v2 = acc[am][an][2] + b0;
                float v3 = acc[am][an][3] + b1;
                if (relu) {
                    v0 = fmaxf(v0, 0.f); v1 = fmaxf(v1, 0.f);
                    v2 = fmaxf(v2, 0.f); v3 = fmaxf(v3, 0.f);
                }
                if (gr0 < NPAT) {
                    Cb[(long)gr0 * NN + gn] = v0;
                    Cb[(long)gr0 * NN + gn + 1] = v1;
                }
                if (gr0 + 8 < NPAT) {
                    Cb[(long)(gr0 + 8) * NN + gn] = v2;
                    Cb[(long)(gr0 + 8) * NN + gn + 1] = v3;
                }
            }
        }
    }
}

// ==================== fused: GEMM1 (252 blocks) + conv2 (1024 blocks) =========
__global__ void __launch_bounds__(256) fusedA_kernel(
        const __nv_bfloat16* __restrict__ A,
        const __nv_bfloat16* __restrict__ B,
        float* __restrict__ C,
        const float* __restrict__ gbias,
        const float* __restrict__ cbias) {
    extern __shared__ char fsm[];
    int blk = blockIdx.x;
    if (blk < 252) {
        gemm_body<128, 64>(blk % 63, blk / 63, A, B, C, gbias, 1,
                           (__nv_bfloat16*)fsm);
    } else {
        int t = blk - 252;
        conv2_body(t & 7, (t >> 3) & 31, t >> 8, cbias, (__half*)fsm);
    }
}

// standalone GEMM2
__global__ void __launch_bounds__(256) gemm2_kernel(
        const __nv_bfloat16* __restrict__ A,
        const __nv_bfloat16* __restrict__ B,
        float* __restrict__ C,
        const float* __restrict__ bias) {
    extern __shared__ char fsm[];
    gemm_body<64, 128>(blockIdx.x, blockIdx.z, A, B, C, bias, 0,
                       (__nv_bfloat16*)fsm);
}

// ==================== conv3 (fp16 smem, 8-ic phases) ====================
__global__ void __launch_bounds__(256) conv3_kernel(const float* __restrict__ w,
                             const float* __restrict__ bias) {
    __shared__ __half sH[8][18][72];
    __shared__ float sW[576];
    int b = blockIdx.z;
    int x0 = blockIdx.x * 64, y0 = blockIdx.y * 16;
    int tid = threadIdx.x;
    for (int i = tid; i < 576; i += 256) sW[i] = w[i];
    int tx = tid & 15, ty = tid >> 4;
    float acc[4] = {0.f, 0.f, 0.f, 0.f};
    for (int cc = 0; cc < 8; cc++) {
        __syncthreads();
        for (int i = tid; i < 1152; i += 256) {
            int ic = i / 144;
            int rem = i - ic * 144;
            int yy = rem >> 3, q = rem & 7;
            int gy = y0 + yy - 1;
            uint4 v = make_uint4(0u, 0u, 0u, 0u);
            if (gy >= 0 && gy < IMGD)
                v = *(const uint4*)&g_h2h[(((long)b * HID + cc * 8 + ic) << 16)
                                          + (gy << 8) + x0 + q * 8];
            *(uint4*)&sH[ic][yy][q * 8] = v;
        }
        for (int i = tid; i < 288; i += 256) {
            int ic = i / 36;
            int rem = i - ic * 36;
            int yy = rem >> 1, side = rem & 1;
            int gy = y0 + yy - 1;
            int gx = side ? x0 + 64 : x0 - 1;
            __half v = __ushort_as_half(0);
            if (gy >= 0 && gy < IMGD && gx >= 0 && gx < IMGD)
                v = g_h2h[(((long)b * HID + cc * 8 + ic) << 16) + (gy << 8) + gx];
            sH[ic][yy][64 + side] = v;
        }
        __syncthreads();
#pragma unroll
        for (int ic = 0; ic < 8; ic++) {
            float rin[3][6];
#pragma unroll
            for (int dy = 0; dy < 3; dy++)
#pragma unroll
                for (int j = 0; j < 6; j++) {
                    int c = tx * 4 + j - 1;
                    int cm = (c < 0) ? 64 : ((c > 63) ? 65 : c);
                    rin[dy][j] = __half2float(sH[ic][ty + dy][cm]);
                }
            float wv[9];
#pragma unroll
            for (int t = 0; t < 9; t++) wv[t] = sW[(cc * 8 + ic) * 9 + t];
#pragma unroll
            for (int dy = 0; dy < 3; dy++)
#pragma unroll
                for (int dx = 0; dx < 3; dx++)
#pragma unroll
                    for (int p = 0; p < 4; p++)
                        acc[p] += rin[dy][p + dx] * wv[dy * 3 + dx];
        }
    }
    float bv = bias[0];
    float4 o;
    o.x = acc[0] + bv; o.y = acc[1] + bv; o.z = acc[2] + bv; o.w = acc[3] + bv;
    *(float4*)&g_tmp2[(long)b * IMGD * IMGD + (y0 + ty) * IMGD + x0 + tx * 4] = o;
}

// ==================== GCN small kernels ====================
__global__ void patch_kernel(const float* __restrict__ in) {
    int idx = blockIdx.x * 256 + threadIdx.x;
    if (idx >= BB * NPAT * 8) return;
    int i = idx & 7;
    int t = idx >> 3;
    int n = t % NPAT;
    int b = t / NPAT;
    int py = n / PH, px = n - py * PH;
    const float* src = in + (long)b * IMGD * IMGD + (py * 4 + i) * IMGD + px * 4;
    float* dst = g_patch + ((long)b * NPAT + n) * PPF + i * 8;
    *(float4*)dst = *(const float4*)src;
    *(float4*)(dst + 4) = *(const float4*)(src + 4);
}

__global__ void __launch_bounds__(256) adjconv_kernel(const float* __restrict__ adj) {
    long idx = (long)blockIdx.x * 256 + threadIdx.x;
    const long TOT = (long)BB * NPAT * (KPAD / 8);
    if (idx >= TOT) return;
    int kq = (int)(idx % (KPAD / 8));
    long row = idx / (KPAD / 8);
    int k0 = kq * 8;
    const float* src = adj + row * NPAT + k0;
    __nv_bfloat16 o[8];
#pragma unroll
    for (int j = 0; j < 8; j++) {
        float v = (k0 + j < NPAT) ? src[j] : 0.f;
        o[j] = __float2bfloat16(v);
    }
    *(uint4*)&g_adjb[row * KPAD + k0] = *(uint4*)o;
}

__global__ void __launch_bounds__(128) gemmA_kernel(const float* __restrict__ w3) {
    __shared__ float sP[32][65];
    __shared__ float sW[64][128];
    int b = blockIdx.y;
    int n0 = blockIdx.x * 32;
    int tid = threadIdx.x;
    for (int l = 0; l < 64; l++) {
        int idx = tid + l * 128;
        sW[idx >> 7][idx & 127] = w3[idx];
    }
    for (int l = 0; l < 16; l++) {
        int idx = tid + l * 128;
        int n = idx >> 6, k = idx & 63;
        float v = 0.f;
        if (n0 + n < NPAT) v = g_patch[((long)b * NPAT + n0 + n) * PPF + k];
        sP[n][k] = v;
    }
    __syncthreads();
    int g = tid;
    float acc[32];
#pragma unroll
    for (int n = 0; n < 32; n++) acc[n] = 0.f;
    for (int k = 0; k < 64; k++) {
        float wv = sW[k][g];
#pragma unroll
        for (int n = 0; n < 32; n++) acc[n] += sP[n][k] * wv;
    }
    __nv_bfloat16* dst = g_supT + ((long)b * GHD + g) * KPAD + n0;
#pragma unroll
    for (int n = 0; n < 32; n++)
        dst[n] = (n0 + n < NPAT) ? __float2bfloat16(acc[n]) : __float2bfloat16(0.f);
}

__global__ void __launch_bounds__(128) gemmB_kernel(const float* __restrict__ w4) {
    __shared__ float sG[32][129];
    __shared__ float sW[64][64];
    int b = blockIdx.y;
    int n0 = blockIdx.x * 32;
    int tid = threadIdx.x;
    int p = tid & 63, half = tid >> 6;
    float acc[16];
#pragma unroll
    for (int i = 0; i < 16; i++) acc[i] = 0.f;
    for (int kc = 0; kc < 2; kc++) {
        __syncthreads();
        for (int l = 0; l < 32; l++) {
            int idx = tid + l * 128;
            int kk = idx >> 6, pp = idx & 63;
            sW[kk][pp] = w4[(kc * 64 + kk) * 64 + pp];
        }
        for (int l = 0; l < 16; l++) {
            int idx = tid + l * 128;
            int n = idx >> 6, kk = idx & 63;
            float v = 0.f;
            if (n0 + n < NPAT) v = g_g[((long)b * NPAT + n0 + n) * GHD + kc * 64 + kk];
            sG[n][kk] = v;
        }
        __syncthreads();
        for (int kk = 0; kk < 64; kk++) {
            float wv = sW[kk][p];
#pragma unroll
            for (int i = 0; i < 16; i++) acc[i] += sG[half * 16 + i][kk] * wv;
        }
    }
    __nv_bfloat16* dst = g_gsupT + ((long)b * PPF + p) * KPAD + n0 + half * 16;
#pragma unroll
    for (int i = 0; i < 16; i++)
        dst[i] = (n0 + half * 16 + i < NPAT) ? __float2bfloat16(acc[i]) : __float2bfloat16(0.f);
}

// ---------------- final: vectorized x4 ----------------
__global__ void final_kernel(const float* __restrict__ in,
                             const float* __restrict__ proj,
                             const float* __restrict__ lam,
                             float* __restrict__ out) {
    int t = blockIdx.x * 256 + threadIdx.x;
    if (t >= BB * IMGD * IMGD / 4) return;
    int q = t & 63;
    int y = (t >> 6) & 255;
    int b = t >> 14;
    long pbase = ((long)b * IMGD * IMGD + y * IMGD + q * 4);
    float4 iv = *(const float4*)&in[pbase];
    float4 pv = *(const float4*)&proj[pbase];
    float4 t2 = *(const float4*)&g_tmp2[pbase];
    float lv = lam[0];

    int tyv = y - 7;
    int py_lo = tyv > 0 ? (tyv + 3) >> 2 : 0;
    int py_hi = min(62, y >> 2);
    int px_lo = q >= 1 ? q - 1 : 0;
    int px_hi = min(62, q);
    float cnt = (float)((py_hi - py_lo + 1) * (px_hi - px_lo + 1));

    float4 s = make_float4(0.f, 0.f, 0.f, 0.f);
    for (int py = py_lo; py <= py_hi; py++) {
        int i = y - 4 * py;
        for (int px = px_lo; px <= px_hi; px++) {
            int j0 = 4 * (q - px);
            const float* g = &g_g2[(((long)b * NPAT + py * PH + px) << 6) + i * 8 + j0];
            float4 v = *(const float4*)g;
            s.x += v.x; s.y += v.y; s.z += v.z; s.w += v.w;
        }
    }
    float ic = 1.f / cnt;
    float4 o;
    o.x = fmaxf(iv.x + lv * (pv.x - iv.x) + t2.x + s.x * ic, 0.f);
    o.y = fmaxf(iv.y + lv * (pv.y - iv.y) + t2.y + s.y * ic, 0.f);
    o.z = fmaxf(iv.z + lv * (pv.z - iv.z) + t2.z + s.z * ic, 0.f);
    o.w = fmaxf(iv.w + lv * (pv.w - iv.w) + t2.w + s.w * ic, 0.f);
    *(float4*)&out[pbase] = o;
}

// ---------------- launch ----------------
extern "C" void kernel_launch(void* const* d_in, const int* in_sizes, int n_in,
                              void* d_out, int out_size) {
    const float* input = (const float*)d_in[0];
    const float* proj  = (const float*)d_in[1];
    const float* adj   = (const float*)d_in[2];
    const float* lam   = (const float*)d_in[3];
    const float* w1 = (const float*)d_in[4];
    const float* b1 = (const float*)d_in[5];
    const float* w2 = (const float*)d_in[6];
    const float* b2 = (const float*)d_in[7];
    const float* w3 = (const float*)d_in[8];
    const float* b3 = (const float*)d_in[9];
    const float* gw3 = (const float*)d_in[10];
    const float* gb3 = (const float*)d_in[11];
    const float* gw4 = (const float*)d_in[12];
    const float* gb4 = (const float*)d_in[13];
    float* out = (float*)d_out;

    __nv_bfloat16 *p_adjb, *p_supT, *p_gsupT;
    float *p_g, *p_g2;
    cudaGetSymbolAddress((void**)&p_adjb, g_adjb);
    cudaGetSymbolAddress((void**)&p_supT, g_supT);
    cudaGetSymbolAddress((void**)&p_gsupT, g_gsupT);
    cudaGetSymbolAddress((void**)&p_g, g_g);
    cudaGetSymbolAddress((void**)&p_g2, g_g2);

    const int FUSED_SMEM = STAGES * (64 * LDT + 128 * LDT) * 2;  // 82944 (>= conv2's 67392)
    const int G2_SMEM = STAGES * (128 * LDT + 64 * LDT) * 2;     // 82944
    cudaFuncSetAttribute((const void*)fusedA_kernel,
                         cudaFuncAttributeMaxDynamicSharedMemorySize, FUSED_SMEM);
    cudaFuncSetAttribute((const void*)gemm2_kernel,
                         cudaFuncAttributeMaxDynamicSharedMemorySize, G2_SMEM);

    {
        long TOT = (long)BB * NPAT * (KPAD / 8);
        adjconv_kernel<<<(int)((TOT + 255) / 256), 256>>>(adj);
    }
    patch_kernel<<<(BB * NPAT * 8 + 255) / 256, 256>>>(input);
    wt_kernel<<<144, 256>>>(w2);
    conv1_kernel<<<dim3(16, 16, BB), 256>>>(input, w1, b1);
    gemmA_kernel<<<dim3(KPAD / 32, BB), 128>>>(gw3);

    // fused: GEMM1 (adj @ supT -> g_g) + conv2 (h1i -> h2h)
    fusedA_kernel<<<252 + 1024, 256, FUSED_SMEM>>>(p_adjb, p_supT, p_g, gb3, b2);

    conv3_kernel<<<dim3(4, 16, BB), 256>>>(w3, b3);
    gemmB_kernel<<<dim3(KPAD / 32, BB), 128>>>(gw4);
    gemm2_kernel<<<dim3(32, 1, BB), 256, G2_SMEM>>>(p_adjb, p_gsupT, p_g2, gb4);

    final_kernel<<<(BB * IMGD * IMGD / 4 + 255) / 256, 256>>>(input, proj, lam, out);
}

// round 17
// speedup vs baseline: 1.1712x; 1.1712x over previous
#include <cuda_runtime.h>
#include <cuda_bf16.h>
#include <cuda_fp16.h>
#include <cstdint>

// ---------------- problem constants ----------------
#define BB   4
#define IMGD 256
#define HID  64
#define PH   63
#define NPAT 3969   // 63*63
#define PPF  64     // 8*8 patch pixels
#define GHD  128
#define KPAD 4032   // 63*64, padded K for tensor GEMM
#define NCHUNK 63   // KPAD / 64 (64 bf16 per pipeline chunk)

// ---------------- scratch (device globals; no runtime alloc) ----------------
__device__ __half g_h1i[(long)BB*IMGD*IMGD*HID];      // conv1 out, [b][y][x][ic] fp16
__device__ __half g_h2h[(long)BB*HID*IMGD*IMGD];      // conv2 out, [b][oc][y][x] fp16
__device__ float g_tmp2[BB*IMGD*IMGD];                // conv3 out
__device__ float g_patch[BB*NPAT*PPF];                // [b][n][64]
__device__ float g_g[(long)BB*NPAT*GHD];              // relu(adj@sup+b3)
__device__ float g_g2[(long)BB*NPAT*PPF];             // adj@gsup+b4
__device__ __nv_bfloat16 g_adjb[(long)BB*NPAT*KPAD];  // adj bf16 K-padded
__device__ __nv_bfloat16 g_supT[(long)BB*GHD*KPAD];   // (patch@W3)^T bf16
__device__ __nv_bfloat16 g_gsupT[(long)BB*PPF*KPAD];  // (g@W4)^T bf16
__device__ __half g_w2t[9*64*64];                     // w2 [tap][oc][ic] fp16

__device__ __forceinline__ uint32_t smem_to_u32(const void* p) {
    uint32_t a;
    asm("{ .reg .u64 t; cvta.to.shared.u64 t, %1; cvt.u32.u64 %0, t; }"
        : "=r"(a) : "l"(p));
    return a;
}
__device__ __forceinline__ void ldmatrix_x4(uint32_t* r, uint32_t addr) {
    asm volatile("ldmatrix.sync.aligned.m8n8.x4.shared.b16 {%0,%1,%2,%3}, [%4];"
                 : "=r"(r[0]), "=r"(r[1]), "=r"(r[2]), "=r"(r[3]) : "r"(addr));
}
__device__ __forceinline__ void ldmatrix_x2(uint32_t* r, uint32_t addr) {
    asm volatile("ldmatrix.sync.aligned.m8n8.x2.shared.b16 {%0,%1}, [%2];"
                 : "=r"(r[0]), "=r"(r[1]) : "r"(addr));
}
__device__ __forceinline__ void mma16816_bf16(float* d, const uint32_t* a, const uint32_t* b) {
    asm volatile(
        "mma.sync.aligned.m16n8k16.row.col.f32.bf16.bf16.f32 "
        "{%0,%1,%2,%3}, {%4,%5,%6,%7}, {%8,%9}, {%0,%1,%2,%3};"
        : "+f"(d[0]), "+f"(d[1]), "+f"(d[2]), "+f"(d[3])
        : "r"(a[0]), "r"(a[1]), "r"(a[2]), "r"(a[3]), "r"(b[0]), "r"(b[1]));
}
__device__ __forceinline__ void mma16816_f16(float* d, const uint32_t* a, const uint32_t* b) {
    asm volatile(
        "mma.sync.aligned.m16n8k16.row.col.f32.f16.f16.f32 "
        "{%0,%1,%2,%3}, {%4,%5,%6,%7}, {%8,%9}, {%0,%1,%2,%3};"
        : "+f"(d[0]), "+f"(d[1]), "+f"(d[2]), "+f"(d[3])
        : "r"(a[0]), "r"(a[1]), "r"(a[2]), "r"(a[3]), "r"(b[0]), "r"(b[1]));
}
__device__ __forceinline__ void cp_async16(uint32_t dst, const void* src, uint32_t bytes) {
    asm volatile("cp.async.cg.shared.global [%0], [%1], 16, %2;"
                 :: "r"(dst), "l"(src), "r"(bytes));
}
#define CP_COMMIT() asm volatile("cp.async.commit_group;" ::: "memory")
#define CP_WAIT(n)  asm volatile("cp.async.wait_group %0;" :: "n"(n) : "memory")

// ==================== weight transform: w2 OIHW -> [tap][oc][ic] fp16 =========
__global__ void wt_kernel(const float* __restrict__ w2) {
    int idx = blockIdx.x * 256 + threadIdx.x;
    if (idx >= 64 * 64 * 9) return;
    int oc = idx / 576, r = idx - oc * 576;
    int ic = r / 9, t = r - ic * 9;
    g_w2t[t * 4096 + oc * 64 + ic] = __float2half(w2[idx]);
}

// ==================== conv1: 1 -> 64, relu, interleaved fp16 out =============
// staging stride 72 halves (144 B, 16B-aligned): 4-way conflicts (vs 32-way at 64)
__global__ void __launch_bounds__(256) conv1_kernel(const float* __restrict__ in,
                             const float* __restrict__ w,
                             const float* __restrict__ bias) {
    __shared__ float sIn[18][18];
    __shared__ float sW[576];
    __shared__ float sB[64];
    __shared__ __half sOut[16 * 16 * 72];   // stride 72
    int b = blockIdx.z;
    int x0 = blockIdx.x * 16, y0 = blockIdx.y * 16;
    int tid = threadIdx.x;
    for (int i = tid; i < 576; i += 256) sW[i] = w[i];
    if (tid < 64) sB[tid] = bias[tid];
    for (int i = tid; i < 324; i += 256) {
        int yy = i / 18, xx = i - yy * 18;
        int gy = y0 + yy - 1, gx = x0 + xx - 1;
        float v = 0.f;
        if (gy >= 0 && gy < IMGD && gx >= 0 && gx < IMGD)
            v = in[(long)b * IMGD * IMGD + gy * IMGD + gx];
        sIn[yy][xx] = v;
    }
    __syncthreads();
    int tx = tid & 15, ty = tid >> 4;
    float r[9];
#pragma unroll
    for (int dy = 0; dy < 3; dy++)
#pragma unroll
        for (int dx = 0; dx < 3; dx++)
            r[dy * 3 + dx] = sIn[ty + dy][tx + dx];
#pragma unroll 1
    for (int oc0 = 0; oc0 < 64; oc0 += 8) {
        __half hv[8];
#pragma unroll
        for (int o = 0; o < 8; o++) {
            float acc = sB[oc0 + o];
#pragma unroll
            for (int t = 0; t < 9; t++) acc += r[t] * sW[(oc0 + o) * 9 + t];
            hv[o] = __float2half(fmaxf(acc, 0.f));
        }
        *(uint4*)&sOut[tid * 72 + oc0] = *(uint4*)hv;
    }
    __syncthreads();
    // copy out: element (px, ic8-group) -> gmem [y][x][ic]
    for (int i = tid; i < 2048; i += 256) {
        int row = i >> 7;            // 0..15 (y)
        int c = i & 127;             // 128 uint4 per row
        int px = c >> 3, icq = c & 7;
        long e = (((long)b * IMGD * IMGD + (y0 + row) * IMGD + x0 + px) << 6) + icq * 8;
        *(uint4*)&g_h1i[e] = *(uint4*)&sOut[(row * 16 + px) * 72 + icq * 8];
    }
}

// ==================== conv2: fp16 HMMA, 9-tap shifted GEMM ====================
#define C2_XH (340 * 72)
#define C2_WH (64 * 72)
__global__ void __launch_bounds__(256) conv2mma_kernel(const float* __restrict__ bias) {
    extern __shared__ __half dsm[];
    __half* X_s = dsm;
    __half* W_s[2] = {dsm + C2_XH, dsm + C2_XH + C2_WH};
    int tid = threadIdx.x, lane = tid & 31, wid = tid >> 5;
    int b = blockIdx.z, y0 = blockIdx.y * 8, x0 = blockIdx.x * 32;
    int wm = (wid & 3) * 64;
    int wn = (wid >> 2) * 32;

    for (int i = tid; i < 2720; i += 256) {
        int pos = i >> 3, q = i & 7;
        int row = pos / 34, col = pos - row * 34;
        int gy = y0 + row - 1, gx = x0 + col - 1;
        uint4 v = make_uint4(0u, 0u, 0u, 0u);
        if (gy >= 0 && gy < IMGD && gx >= 0 && gx < IMGD)
            v = *(const uint4*)&g_h1i[(((long)b * IMGD * IMGD + gy * IMGD + gx) << 6) + q * 8];
        *(uint4*)&X_s[pos * 72 + q * 8] = v;
    }
    for (int i = tid; i < 512; i += 256) {
        int oc = i >> 3, q = i & 7;
        *(uint4*)&W_s[0][oc * 72 + q * 8] = *(const uint4*)&g_w2t[oc * 64 + q * 8];
    }
    __syncthreads();

    float acc[4][4][4];
#pragma unroll
    for (int i = 0; i < 4; i++)
#pragma unroll
        for (int j = 0; j < 4; j++)
#pragma unroll
            for (int q = 0; q < 4; q++) acc[i][j][q] = 0.f;

    uint32_t xb = smem_to_u32(X_s);
    uint32_t wb[2] = {smem_to_u32(W_s[0]), smem_to_u32(W_s[1])};

    uint32_t abase[4];
#pragma unroll
    for (int am = 0; am < 4; am++) {
        int p0 = wm + am * 16;
        abase[am] = xb + (uint32_t)((((p0 >> 5) * 34) + (p0 & 31) + (lane & 15)) * 144)
                       + (uint32_t)((lane >> 4) * 16);
    }
    uint32_t bbase[4];
#pragma unroll
    for (int an = 0; an < 4; an++)
        bbase[an] = (uint32_t)((wn + an * 8 + (lane & 7)) * 144)
                  + (uint32_t)(((lane >> 3) & 1) * 16);

    for (int tap = 0; tap < 9; tap++) {
        int cur = tap & 1;
        if (tap < 8) {
            const __half* src = g_w2t + (tap + 1) * 4096;
            for (int i = tid; i < 512; i += 256) {
                int oc = i >> 3, q = i & 7;
                *(uint4*)&W_s[cur ^ 1][oc * 72 + q * 8] = *(const uint4*)&src[oc * 64 + q * 8];
            }
        }
        int dy = tap / 3, dx = tap - dy * 3;
        uint32_t toff = (uint32_t)((dy * 34 + dx) * 144);
#pragma unroll
        for (int kb = 0; kb < 64; kb += 16) {
            uint32_t af[4][4], bf[4][2];
#pragma unroll
            for (int am = 0; am < 4; am++)
                ldmatrix_x4(af[am], abase[am] + toff + kb * 2);
#pragma unroll
            for (int an = 0; an < 4; an++)
                ldmatrix_x2(bf[an], wb[cur] + bbase[an] + kb * 2);
#pragma unroll
            for (int am = 0; am < 4; am++)
#pragma unroll
                for (int an = 0; an < 4; an++)
                    mma16816_f16(acc[am][an], af[am], bf[an]);
        }
        __syncthreads();
    }

    int r0 = lane >> 2, c0l = (lane & 3) * 2;
#pragma unroll
    for (int am = 0; am < 4; am++) {
#pragma unroll
        for (int an = 0; an < 4; an++) {
            int oc = wn + an * 8 + c0l;
            float b0 = bias[oc], b1 = bias[oc + 1];
#pragma unroll
            for (int h = 0; h < 2; h++) {
                int p = wm + am * 16 + r0 + h * 8;
                int rr = p >> 5, cc = p & 31;
                long o = (((long)b * HID + oc) << 16) + ((y0 + rr) << 8) + (x0 + cc);
                g_h2h[o] = __float2half(fmaxf(acc[am][an][h * 2 + 0] + b0, 0.f));
                g_h2h[o + (1L << 16)] = __float2half(fmaxf(acc[am][an][h * 2 + 1] + b1, 0.f));
            }
        }
    }
}

// ==================== conv3: 64 -> 1, 3x3 SAME (fp16 smem, 8-ic phases) =======
__global__ void __launch_bounds__(256) conv3_kernel(const float* __restrict__ w,
                             const float* __restrict__ bias) {
    __shared__ __half sH[8][18][72];
    __shared__ float sW[576];
    int b = blockIdx.z;
    int x0 = blockIdx.x * 64, y0 = blockIdx.y * 16;
    int tid = threadIdx.x;
    for (int i = tid; i < 576; i += 256) sW[i] = w[i];
    int tx = tid & 15, ty = tid >> 4;
    float acc[4] = {0.f, 0.f, 0.f, 0.f};
    for (int cc = 0; cc < 8; cc++) {
        __syncthreads();
        for (int i = tid; i < 1152; i += 256) {
            int ic = i / 144;
            int rem = i - ic * 144;
            int yy = rem >> 3, q = rem & 7;
            int gy = y0 + yy - 1;
            uint4 v = make_uint4(0u, 0u, 0u, 0u);
            if (gy >= 0 && gy < IMGD)
                v = *(const uint4*)&g_h2h[(((long)b * HID + cc * 8 + ic) << 16)
                                          + (gy << 8) + x0 + q * 8];
            *(uint4*)&sH[ic][yy][q * 8] = v;
        }
        for (int i = tid; i < 288; i += 256) {
            int ic = i / 36;
            int rem = i - ic * 36;
            int yy = rem >> 1, side = rem & 1;
            int gy = y0 + yy - 1;
            int gx = side ? x0 + 64 : x0 - 1;
            __half v = __ushort_as_half(0);
            if (gy >= 0 && gy < IMGD && gx >= 0 && gx < IMGD)
                v = g_h2h[(((long)b * HID + cc * 8 + ic) << 16) + (gy << 8) + gx];
            sH[ic][yy][64 + side] = v;
        }
        __syncthreads();
#pragma unroll
        for (int ic = 0; ic < 8; ic++) {
            float rin[3][6];
#pragma unroll
            for (int dy = 0; dy < 3; dy++)
#pragma unroll
                for (int j = 0; j < 6; j++) {
                    int c = tx * 4 + j - 1;
                    int cm = (c < 0) ? 64 : ((c > 63) ? 65 : c);
                    rin[dy][j] = __half2float(sH[ic][ty + dy][cm]);
                }
            float wv[9];
#pragma unroll
            for (int t = 0; t < 9; t++) wv[t] = sW[(cc * 8 + ic) * 9 + t];
#pragma unroll
            for (int dy = 0; dy < 3; dy++)
#pragma unroll
                for (int dx = 0; dx < 3; dx++)
#pragma unroll
                    for (int p = 0; p < 4; p++)
                        acc[p] += rin[dy][p + dx] * wv[dy * 3 + dx];
        }
    }
    float bv = bias[0];
    float4 o;
    o.x = acc[0] + bv; o.y = acc[1] + bv; o.z = acc[2] + bv; o.w = acc[3] + bv;
    *(float4*)&g_tmp2[(long)b * IMGD * IMGD + (y0 + ty) * IMGD + x0 + tx * 4] = o;
}

// ==================== GCN branch ====================

__global__ void patch_kernel(const float* __restrict__ in) {
    int idx = blockIdx.x * 256 + threadIdx.x;
    if (idx >= BB * NPAT * 8) return;
    int i = idx & 7;
    int t = idx >> 3;
    int n = t % NPAT;
    int b = t / NPAT;
    int py = n / PH, px = n - py * PH;
    const float* src = in + (long)b * IMGD * IMGD + (py * 4 + i) * IMGD + px * 4;
    float* dst = g_patch + ((long)b * NPAT + n) * PPF + i * 8;
    *(float4*)dst = *(const float4*)src;
    *(float4*)(dst + 4) = *(const float4*)(src + 4);
}

__global__ void __launch_bounds__(256) adjconv_kernel(const float* __restrict__ adj) {
    long idx = (long)blockIdx.x * 256 + threadIdx.x;
    const long TOT = (long)BB * NPAT * (KPAD / 8);
    if (idx >= TOT) return;
    int kq = (int)(idx % (KPAD / 8));
    long row = idx / (KPAD / 8);
    int k0 = kq * 8;
    const float* src = adj + row * NPAT + k0;
    __nv_bfloat16 o[8];
#pragma unroll
    for (int j = 0; j < 8; j++) {
        float v = (k0 + j < NPAT) ? src[j] : 0.f;
        o[j] = __float2bfloat16(v);
    }
    *(uint4*)&g_adjb[row * KPAD + k0] = *(uint4*)o;
}

__global__ void __launch_bounds__(128) gemmA_kernel(const float* __restrict__ w3) {
    __shared__ float sP[32][65];
    __shared__ float sW[64][128];
    int b = blockIdx.y;
    int n0 = blockIdx.x * 32;
    int tid = threadIdx.x;
    for (int l = 0; l < 64; l++) {
        int idx = tid + l * 128;
        sW[idx >> 7][idx & 127] = w3[idx];
    }
    for (int l = 0; l < 16; l++) {
        int idx = tid + l * 128;
        int n = idx >> 6, k = idx & 63;
        float v = 0.f;
        if (n0 + n < NPAT) v = g_patch[((long)b * NPAT + n0 + n) * PPF + k];
        sP[n][k] = v;
    }
    __syncthreads();
    int g = tid;
    float acc[32];
#pragma unroll
    for (int n = 0; n < 32; n++) acc[n] = 0.f;
    for (int k = 0; k < 64; k++) {
        float wv = sW[k][g];
#pragma unroll
        for (int n = 0; n < 32; n++) acc[n] += sP[n][k] * wv;
    }
    __nv_bfloat16* dst = g_supT + ((long)b * GHD + g) * KPAD + n0;
#pragma unroll
    for (int n = 0; n < 32; n++)
        dst[n] = (n0 + n < NPAT) ? __float2bfloat16(acc[n]) : __float2bfloat16(0.f);
}

__global__ void __launch_bounds__(128) gemmB_kernel(const float* __restrict__ w4) {
    __shared__ float sG[32][129];
    __shared__ float sW[64][64];
    int b = blockIdx.y;
    int n0 = blockIdx.x * 32;
    int tid = threadIdx.x;
    int p = tid & 63, half = tid >> 6;
    float acc[16];
#pragma unroll
    for (int i = 0; i < 16; i++) acc[i] = 0.f;
    for (int kc = 0; kc < 2; kc++) {
        __syncthreads();
        for (int l = 0; l < 32; l++) {
            int idx = tid + l * 128;
            int kk = idx >> 6, pp = idx & 63;
            sW[kk][pp] = w4[(kc * 64 + kk) * 64 + pp];
        }
        for (int l = 0; l < 16; l++) {
            int idx = tid + l * 128;
            int n = idx >> 6, kk = idx & 63;
            float v = 0.f;
            if (n0 + n < NPAT) v = g_g[((long)b * NPAT + n0 + n) * GHD + kc * 64 + kk];
            sG[n][kk] = v;
        }
        __syncthreads();
        for (int kk = 0; kk < 64; kk++) {
            float wv = sW[kk][p];
#pragma unroll
            for (int i = 0; i < 16; i++) acc[i] += sG[half * 16 + i][kk] * wv;
        }
    }
    __nv_bfloat16* dst = g_gsupT + ((long)b * PPF + p) * KPAD + n0 + half * 16;
#pragma unroll
    for (int i = 0; i < 16; i++)
        dst[i] = (n0 + half * 16 + i < NPAT) ? __float2bfloat16(acc[i]) : __float2bfloat16(0.f);
}

// ---------------- big HMMA GEMM, cp.async 3-stage, BK=64 bf16 ----------------
#define LDT 72
#define STAGES 3

template<int NN, int BM>
__global__ void __launch_bounds__(256) mma_gemm_kernel(
        const __nv_bfloat16* __restrict__ A,
        const __nv_bfloat16* __restrict__ B,
        float* __restrict__ C,
        const float* __restrict__ bias, int relu) {
    constexpr int WNw = NN / 2;
    constexpr int NA = WNw / 8;
    constexpr int MW = BM / 2;
    constexpr int AM = MW / 16;
    constexpr int ASTG = BM * LDT;
    constexpr int BSTG = NN * LDT;
    constexpr int NAU = BM / 32;
    constexpr int NBU = NN * 8 / 256;
    constexpr int RSTR = WNw + 1;
    extern __shared__ __nv_bfloat16 gsm[];
    __nv_bfloat16* A_s = gsm;
    __nv_bfloat16* B_s = gsm + STAGES * ASTG;

    int tid = threadIdx.x;
    int lane = tid & 31;
    int wid = tid >> 5;
    int mi = wid & 1, ni = (wid >> 1) & 1, kg = wid >> 2;
    int wm = mi * MW;
    int wn = ni * WNw;
    int bz = blockIdx.z;
    int m0 = blockIdx.x * BM;

    const __nv_bfloat16* Ab = A + (long)bz * NPAT * KPAD;
    const __nv_bfloat16* Bb = B + (long)bz * NN * KPAD;
    float* Cb = C + (long)bz * NPAT * NN;

    float acc[AM][NA][4];
#pragma unroll
    for (int i = 0; i < AM; i++)
#pragma unroll
        for (int j = 0; j < NA; j++)
#pragma unroll
            for (int q = 0; q < 4; q++) acc[i][j][q] = 0.f;

    int a_row[NAU], a_part[NAU];
    uint32_t a_dst[NAU], a_bytes[NAU];
    const __nv_bfloat16* a_src[NAU];
#pragma unroll
    for (int l = 0; l < NAU; l++) {
        int u = tid + l * 256;
        a_row[l] = u >> 3; a_part[l] = u & 7;
        int gm = m0 + a_row[l];
        a_bytes[l] = (gm < NPAT) ? 16u : 0u;
        int gmc = gm < NPAT ? gm : NPAT - 1;
        a_src[l] = Ab + (long)gmc * KPAD + a_part[l] * 8;
        a_dst[l] = smem_to_u32(&A_s[a_row[l] * LDT + a_part[l] * 8]);
    }
    uint32_t b_dst[NBU];
    const __nv_bfloat16* b_src[NBU];
#pragma unroll
    for (int l = 0; l < NBU; l++) {
        int u = tid + l * 256;
        int row = u >> 3, part = u & 7;
        b_src[l] = Bb + (long)row * KPAD + part * 8;
        b_dst[l] = smem_to_u32(&B_s[row * LDT + part * 8]);
    }

    auto issue = [&](int c) {
        int s = c % STAGES;
        long kb = (long)c * 64;
#pragma unroll
        for (int l = 0; l < NAU; l++)
            cp_async16(a_dst[l] + s * (ASTG * 2), a_src[l] + kb, a_bytes[l]);
#pragma unroll
        for (int l = 0; l < NBU; l++)
            cp_async16(b_dst[l] + s * (BSTG * 2), b_src[l] + kb, 16u);
        CP_COMMIT();
    };

#pragma unroll
    for (int s = 0; s < STAGES - 1; s++) issue(s);

    uint32_t a_base0 = smem_to_u32(A_s);
    uint32_t b_base0 = smem_to_u32(B_s);
    uint32_t kks = (uint32_t)(kg * 64);

    for (int c = 0; c < NCHUNK; c++) {
        CP_WAIT(STAGES - 2);
        __syncthreads();
        int s = c % STAGES;
        uint32_t a_base = a_base0 + s * (ASTG * 2);
        uint32_t b_base = b_base0 + s * (BSTG * 2);
#pragma unroll
        for (int ks = 0; ks < 2; ks++) {
            uint32_t af[AM][4];
#pragma unroll
            for (int am = 0; am < AM; am++) {
                uint32_t addr = a_base +
                    (uint32_t)((wm + am * 16 + (lane & 15)) * (LDT * 2)) +
                    kks + (uint32_t)(ks * 32 + (lane >> 4) * 16);
                ldmatrix_x4(af[am], addr);
            }
            uint32_t bf[NA][2];
#pragma unroll
            for (int an = 0; an < NA; an++) {
                uint32_t addr = b_base +
                    (uint32_t)((wn + an * 8 + (lane & 7)) * (LDT * 2)) +
                    kks + (uint32_t)(ks * 32 + ((lane >> 3) & 1) * 16);
                ldmatrix_x2(bf[an], addr);
            }
#pragma unroll
            for (int am = 0; am < AM; am++)
#pragma unroll
                for (int an = 0; an < NA; an++)
                    mma16816_bf16(acc[am][an], af[am], bf[an]);
        }
        if (c + STAGES - 1 < NCHUNK) issue(c + STAGES - 1);
        else CP_COMMIT();
    }

    CP_WAIT(0);
    __syncthreads();
    int r0 = lane >> 2, c0 = (lane & 3) * 2;
    float* red = (float*)gsm;
    int region = (mi * 2 + ni) * (MW * RSTR);
    if (kg == 1) {
#pragma unroll
        for (int am = 0; am < AM; am++)
#pragma unroll
            for (int an = 0; an < NA; an++)
#pragma unroll
                for (int q = 0; q < 4; q++) {
                    int row = am * 16 + r0 + ((q >> 1) << 3);
                    int col = an * 8 + c0 + (q & 1);
                    red[region + row * RSTR + col] = acc[am][an][q];
                }
    }
    __syncthreads();
    if (kg == 0) {
#pragma unroll
        for (int am = 0; am < AM; am++)
#pragma unroll
            for (int an = 0; an < NA; an++)
#pragma unroll
                for (int q = 0; q < 4; q++) {
                    int row = am * 16 + r0 + ((q >> 1) << 3);
                    int col = an * 8 + c0 + (q & 1);
                    acc[am][an][q] += red[region + row * RSTR + col];
                }
#pragma unroll
        for (int am = 0; am < AM; am++) {
#pragma unroll
            for (int an = 0; an < NA; an++) {
                int gn = wn + an * 8 + c0;
                float b0 = bias[gn], b1 = bias[gn + 1];
                int gr0 = m0 + wm + am * 16 + r0;
                float v0 = acc[am][an][0] + b0;
                float v1 = acc[am][an][1] + b1;
                float v2 = acc[am][an][2] + b0;
                float v3 = acc[am][an][3] + b1;
                if (relu) {
                    v0 = fmaxf(v0, 0.f); v1 = fmaxf(v1, 0.f);
                    v2 = fmaxf(v2, 0.f); v3 = fmaxf(v3, 0.f);
                }
                if (gr0 < NPAT) {
                    Cb[(long)gr0 * NN + gn] = v0;
                    Cb[(long)gr0 * NN + gn + 1] = v1;
                }
                if (gr0 + 8 < NPAT) {
                    Cb[(long)(gr0 + 8) * NN + gn] = v2;
                    Cb[(long)(gr0 + 8) * NN + gn + 1] = v3;
                }
            }
        }
    }
}

// ---------------- final: vectorized x4 ----------------
__global__ void final_kernel(const float* __restrict__ in,
                             const float* __restrict__ proj,
                             const float* __restrict__ lam,
                             float* __restrict__ out) {
    int t = blockIdx.x * 256 + threadIdx.x;
    if (t >= BB * IMGD * IMGD / 4) return;
    int q = t & 63;
    int y = (t >> 6) & 255;
    int b = t >> 14;
    long pbase = ((long)b * IMGD * IMGD + y * IMGD + q * 4);
    float4 iv = *(const float4*)&in[pbase];
    float4 pv = *(const float4*)&proj[pbase];
    float4 t2 = *(const float4*)&g_tmp2[pbase];
    float lv = lam[0];

    int tyv = y - 7;
    int py_lo = tyv > 0 ? (tyv + 3) >> 2 : 0;
    int py_hi = min(62, y >> 2);
    int px_lo = q >= 1 ? q - 1 : 0;
    int px_hi = min(62, q);
    float cnt = (float)((py_hi - py_lo + 1) * (px_hi - px_lo + 1));

    float4 s = make_float4(0.f, 0.f, 0.f, 0.f);
    for (int py = py_lo; py <= py_hi; py++) {
        int i = y - 4 * py;
        for (int px = px_lo; px <= px_hi; px++) {
            int j0 = 4 * (q - px);
            const float* g = &g_g2[(((long)b * NPAT + py * PH + px) << 6) + i * 8 + j0];
            float4 v = *(const float4*)g;
            s.x += v.x; s.y += v.y; s.z += v.z; s.w += v.w;
        }
    }
    float ic = 1.f / cnt;
    float4 o;
    o.x = fmaxf(iv.x + lv * (pv.x - iv.x) + t2.x + s.x * ic, 0.f);
    o.y = fmaxf(iv.y + lv * (pv.y - iv.y) + t2.y + s.y * ic, 0.f);
    o.z = fmaxf(iv.z + lv * (pv.z - iv.z) + t2.z + s.z * ic, 0.f);
    o.w = fmaxf(iv.w + lv * (pv.w - iv.w) + t2.w + s.w * ic, 0.f);
    *(float4*)&out[pbase] = o;
}

// ---------------- launch ----------------
extern "C" void kernel_launch(void* const* d_in, const int* in_sizes, int n_in,
                              void* d_out, int out_size) {
    const float* input = (const float*)d_in[0];
    const float* proj  = (const float*)d_in[1];
    const float* adj   = (const float*)d_in[2];
    const float* lam   = (const float*)d_in[3];
    const float* w1 = (const float*)d_in[4];
    const float* b1 = (const float*)d_in[5];
    const float* w2 = (const float*)d_in[6];
    const float* b2 = (const float*)d_in[7];
    const float* w3 = (const float*)d_in[8];
    const float* b3 = (const float*)d_in[9];
    const float* gw3 = (const float*)d_in[10];
    const float* gb3 = (const float*)d_in[11];
    const float* gw4 = (const float*)d_in[12];
    const float* gb4 = (const float*)d_in[13];
    float* out = (float*)d_out;

    __nv_bfloat16 *p_adjb, *p_supT, *p_gsupT;
    float *p_g, *p_g2;
    cudaGetSymbolAddress((void**)&p_adjb, g_adjb);
    cudaGetSymbolAddress((void**)&p_supT, g_supT);
    cudaGetSymbolAddress((void**)&p_gsupT, g_gsupT);
    cudaGetSymbolAddress((void**)&p_g, g_g);
    cudaGetSymbolAddress((void**)&p_g2, g_g2);

    const int C2_SMEM = (C2_XH + 2 * C2_WH) * 2;
    cudaFuncSetAttribute((const void*)conv2mma_kernel,
                         cudaFuncAttributeMaxDynamicSharedMemorySize, C2_SMEM);
    const int G1_SMEM = STAGES * (64 * LDT + 128 * LDT) * 2;   // 82944
    const int G2_SMEM = STAGES * (128 * LDT + 64 * LDT) * 2;   // 82944
    cudaFuncSetAttribute((const void*)mma_gemm_kernel<128, 64>,
                         cudaFuncAttributeMaxDynamicSharedMemorySize, G1_SMEM);
    cudaFuncSetAttribute((const void*)mma_gemm_kernel<64, 128>,
                         cudaFuncAttributeMaxDynamicSharedMemorySize, G2_SMEM);

    {
        long TOT = (long)BB * NPAT * (KPAD / 8);
        adjconv_kernel<<<(int)((TOT + 255) / 256), 256>>>(adj);
    }
    patch_kernel<<<(BB * NPAT * 8 + 255) / 256, 256>>>(input);
    gemmA_kernel<<<dim3(KPAD / 32, BB), 128>>>(gw3);
    mma_gemm_kernel<128, 64><<<dim3(63, 1, BB), 256, G1_SMEM>>>(p_adjb, p_supT, p_g, gb3, 1);

    wt_kernel<<<144, 256>>>(w2);
    conv1_kernel<<<dim3(16, 16, BB), 256>>>(input, w1, b1);
    conv2mma_kernel<<<dim3(8, 32, BB), 256, C2_SMEM>>>(b2);
    conv3_kernel<<<dim3(4, 16, BB), 256>>>(w3, b3);

    gemmB_kernel<<<dim3(KPAD / 32, BB), 128>>>(gw4);
    mma_gemm_kernel<64, 128><<<dim3(32, 1, BB), 256, G2_SMEM>>>(p_adjb, p_gsupT, p_g2, gb4, 0);

    final_kernel<<<(BB * IMGD * IMGD / 4 + 255) / 256, 256>>>(input, proj, lam, out);
}